// round 2
// baseline (speedup 1.0000x reference)
#include <cuda_runtime.h>
#include <math.h>

#define B_TOT   262144
#define THREADS 256
#define BLOCKS  (B_TOT / THREADS)

// ---- shared memory layout (in floats) ----
#define OFF_W1P   0        // 128 rows x 14 pairs (28 floats)  = 3584
#define OFF_B1    3584     // 128
#define OFF_W2G   3712     // 128 rows x 64 pairs (128 floats) = 16384
#define OFF_G2    20096    // 128
#define OFF_C2    20224    // 128
#define OFF_W3G   20352    // 128 rows x 4 pairs (8 floats)    = 1024
#define OFF_G3    21376    // 8
#define OFF_C3    21384    // 8
#define OFF_STAGE 21392    // 64 pairs x 256 threads x 2 floats = 32768
#define SMEM_FLOATS (OFF_STAGE + 32768)          // 54160
#define SMEM_BYTES  (SMEM_FLOATS * 4)            // 216640 B

typedef unsigned long long u64;

static __device__ __forceinline__ u64 pk2(float lo, float hi) {
    u64 r; asm("mov.b64 %0,{%1,%2};" : "=l"(r) : "f"(lo), "f"(hi)); return r;
}
static __device__ __forceinline__ void upk2(u64 v, float &lo, float &hi) {
    asm("mov.b64 {%0,%1},%2;" : "=f"(lo), "=f"(hi) : "l"(v));
}
static __device__ __forceinline__ u64 ffma2(u64 a, u64 b, u64 c) {
    u64 d; asm("fma.rn.f32x2 %0,%1,%2,%3;" : "=l"(d) : "l"(a), "l"(b), "l"(c)); return d;
}
static __device__ __forceinline__ u64 fadd2(u64 a, u64 b) {
    u64 d; asm("add.rn.f32x2 %0,%1,%2;" : "=l"(d) : "l"(a), "l"(b)); return d;
}

static __device__ __forceinline__ float gelu_exact(float x) {
    return 0.5f * x * (1.0f + erff(x * 0.70710678118654752f));
}

// One FK joint update: cumul = cumul @ (Rf @ Rz(theta)); translation first.
// Rf entries are compile-time 0/+-1 constants -> folded by the compiler.
#define FKJ(F00,F01,F02,F10,F11,F12,F20,F21,F22,PX,PY,PZ,TH) do {              \
    float s_, c_; __sincosf((TH), &s_, &c_);                                   \
    tx += r00*(PX) + r01*(PY) + r02*(PZ);                                      \
    ty += r10*(PX) + r11*(PY) + r12*(PZ);                                      \
    tz += r20*(PX) + r21*(PY) + r22*(PZ);                                      \
    float A0 = r00*(F00) + r01*(F10) + r02*(F20);                              \
    float A1 = r10*(F00) + r11*(F10) + r12*(F20);                              \
    float A2 = r20*(F00) + r21*(F10) + r22*(F20);                              \
    float B0 = r00*(F01) + r01*(F11) + r02*(F21);                              \
    float B1 = r10*(F01) + r11*(F11) + r12*(F21);                              \
    float B2 = r20*(F01) + r21*(F11) + r22*(F21);                              \
    float C0 = r00*(F02) + r01*(F12) + r02*(F22);                              \
    float C1 = r10*(F02) + r11*(F12) + r12*(F22);                              \
    float C2v = r20*(F02) + r21*(F12) + r22*(F22);                             \
    r00 = c_*A0 + s_*B0;  r01 = c_*B0 - s_*A0;  r02 = C0;                      \
    r10 = c_*A1 + s_*B1;  r11 = c_*B1 - s_*A1;  r12 = C1;                      \
    r20 = c_*A2 + s_*B2;  r21 = c_*B2 - s_*A2;  r22 = C2v;                     \
} while (0)

__global__ __launch_bounds__(THREADS, 1)
void irm_kernel(const float* __restrict__ ang0,  const float* __restrict__ tgt2d,
                const float* __restrict__ camK,  const float* __restrict__ Rext,
                const float* __restrict__ text,  const int* __restrict__ vmask,
                const float* __restrict__ W1,    const float* __restrict__ b1,
                const float* __restrict__ g1,    const float* __restrict__ be1,
                const float* __restrict__ W2,    const float* __restrict__ b2,
                const float* __restrict__ g2,    const float* __restrict__ be2,
                const float* __restrict__ W3,    const float* __restrict__ b3,
                const float* __restrict__ slog,  float* __restrict__ out)
{
    extern __shared__ float smf[];
    const int tid = threadIdx.x;

    // ================= per-CTA weight preprocessing =================
    // W1 packed: row j holds pairs (W1[2p][j], W1[2p+1][j])
    for (int idx = tid; idx < 1792; idx += THREADS) {
        int j = idx & 127, p = idx >> 7;        // p in [0,14)
        smf[OFF_W1P + j*28 + p*2]     = W1[(2*p)  *128 + j];
        smf[OFF_W1P + j*28 + p*2 + 1] = W1[(2*p+1)*128 + j];
    }
    if (tid < 128) smf[OFF_B1 + tid] = b1[tid];
    // W2 with g1 folded in (LN1 fold): row j pairs (g1[2p]W2[2p][j], g1[2p+1]W2[2p+1][j])
    for (int idx = tid; idx < 8192; idx += THREADS) {
        int j = idx & 127, p = idx >> 7;        // p in [0,64)
        smf[OFF_W2G + j*128 + p*2]     = g1[2*p]   * W2[(2*p)  *128 + j];
        smf[OFF_W2G + j*128 + p*2 + 1] = g1[2*p+1] * W2[(2*p+1)*128 + j];
    }
    if (tid < 128) {  // G2[j] = sum_k g1[k]W2[k][j];  C2[j] = sum_k be1[k]W2[k][j] + b2[j]
        float ga = 0.f, ca = 0.f;
        for (int k = 0; k < 128; k++) {
            float w = W2[k*128 + tid];
            ga += g1[k] * w;  ca += be1[k] * w;
        }
        smf[OFF_G2 + tid] = ga;  smf[OFF_C2 + tid] = ca + b2[tid];
    }
    // W3 with g2 folded (LN2 fold): row k pairs over output jj (pad jj=7 -> 0)
    for (int idx = tid; idx < 512; idx += THREADS) {
        int k = idx & 127, p = idx >> 7;        // p in [0,4)
        float gk = g2[k];
        int j0 = 2*p, j1 = 2*p + 1;
        smf[OFF_W3G + k*8 + p*2]     = gk * W3[k*7 + j0];
        smf[OFF_W3G + k*8 + p*2 + 1] = (j1 < 7) ? gk * W3[k*7 + j1] : 0.0f;
    }
    if (tid < 8) {
        float ga = 0.f, ca = 0.f;
        if (tid < 7) {
            for (int k = 0; k < 128; k++) {
                float w = W3[k*7 + tid];
                ga += g2[k] * w;  ca += be2[k] * w;
            }
            ca += b3[tid];
        }
        smf[OFF_G3 + tid] = ga;  smf[OFF_C3 + tid] = ca;
    }
    __syncthreads();

    // ================= per-sample state =================
    const int s = blockIdx.x * THREADS + tid;
    float th[7];
#pragma unroll
    for (int j = 0; j < 7; j++) th[j] = ang0[s*7 + j];
    const float vm = (vmask[s] != 0) ? 1.0f : 0.0f;
    const float ss0 = 1.0f / (1.0f + expf(-slog[0]));
    const float ss1 = 1.0f / (1.0f + expf(-slog[1]));
    const float ss2 = 1.0f / (1.0f + expf(-slog[2]));

    float* const outTheta = out;
    float* const outKp    = out + (size_t)B_TOT * 7;
    float* const outAng   = out + (size_t)B_TOT * 28;   // (4,B,7)
    float* const outAllKp = out + (size_t)B_TOT * 56;   // (4,B,7,3)

#pragma unroll
    for (int j = 0; j < 7; j++) outAng[(size_t)s*7 + j] = th[j];   // all_angles[0]

    float kx[7], ky[7], kz[7];
    float* const stg = smf + OFF_STAGE + tid * 2;

    for (int it = 0; it < 4; ++it) {
        // ---------------- FK ----------------
        float r00=1.f,r01=0.f,r02=0.f, r10=0.f,r11=1.f,r12=0.f, r20=0.f,r21=0.f,r22=1.f;
        float tx=0.f, ty=0.f, tz=0.f;
        FKJ(1,0,0,  0,1,0,  0,0,1,   0.f,      0.f,     0.333f, th[0]);              // ts1
        FKJ(1,0,0,  0,0,1,  0,-1,0,  0.f,      0.f,     0.f,    th[1]);              // ts2
        kx[1]=tx; ky[1]=ty; kz[1]=tz;
        FKJ(1,0,0,  0,0,-1, 0,1,0,   0.f,     -0.316f,  0.f,    th[2]);              // ts3
        kx[2]=tx; ky[2]=ty; kz[2]=tz;
        FKJ(1,0,0,  0,0,-1, 0,1,0,   0.0825f,  0.f,     0.f,    th[3]);              // ts4
        kx[3]=tx; ky[3]=ty; kz[3]=tz;
        FKJ(1,0,0,  0,0,1,  0,-1,0, -0.0825f,  0.384f,  0.f,    th[4]);              // ts5
        FKJ(1,0,0,  0,0,-1, 0,1,0,   0.f,      0.f,     0.f,    th[5]);              // ts6
        kx[4]=tx; ky[4]=ty; kz[4]=tz;
        FKJ(1,0,0,  0,0,-1, 0,1,0,   0.088f,   0.f,     0.f,    th[6]);              // ts7
        kx[5]=tx; ky[5]=ty; kz[5]=tz;
        kx[6]=tx + 0.107f*r02; ky[6]=ty + 0.107f*r12; kz[6]=tz + 0.107f*r22;         // ts9
        kx[0]=0.f; ky[0]=0.f; kz[0]=0.f;                                             // ts0

        {   // store all_kp[it]
            float* p = outAllKp + ((size_t)it * B_TOT + s) * 21;
#pragma unroll
            for (int k = 0; k < 7; k++) { p[3*k]=kx[k]; p[3*k+1]=ky[k]; p[3*k+2]=kz[k]; }
        }
        if (it == 3) break;

        // ---------------- projection + residual -> x ----------------
        float re[9], Kc[9], te[3];
#pragma unroll
        for (int i = 0; i < 9; i++) { re[i] = Rext[(size_t)s*9 + i]; Kc[i] = camK[(size_t)s*9 + i]; }
#pragma unroll
        for (int i = 0; i < 3; i++) te[i] = text[(size_t)s*3 + i];

        u64 xp[14];
        float dmag[7];
#pragma unroll
        for (int k = 0; k < 7; k++) {
            float cxm = re[0]*kx[k] + re[1]*ky[k] + re[2]*kz[k] + te[0];
            float cym = re[3]*kx[k] + re[4]*ky[k] + re[5]*kz[k] + te[1];
            float czm = re[6]*kx[k] + re[7]*ky[k] + re[8]*kz[k] + te[2];
            float z   = fmaxf(czm, 1e-6f);
            float iz  = 1.0f / z;
            float nx = cxm*iz, ny = cym*iz, nz = czm*iz;
            float u = Kc[0]*nx + Kc[1]*ny + Kc[2]*nz;
            float v = Kc[3]*nx + Kc[4]*ny + Kc[5]*nz;
            float du = (tgt2d[(size_t)s*14 + 2*k    ] - u) * vm;
            float dv = (tgt2d[(size_t)s*14 + 2*k + 1] - v) * vm;
            xp[k] = pk2(du, dv);
            dmag[k] = sqrtf(du*du + dv*dv);
        }
        xp[7]  = pk2(th[0], th[1]);   xp[8]  = pk2(th[2], th[3]);
        xp[9]  = pk2(th[4], th[5]);   xp[10] = pk2(th[6], dmag[0]);
        xp[11] = pk2(dmag[1], dmag[2]); xp[12] = pk2(dmag[3], dmag[4]);
        xp[13] = pk2(dmag[5], dmag[6]);

        // ---------------- layer 1: x@W1+b1 -> GELU, stats for LN1 ----------------
        float sum1 = 0.f, sq1 = 0.f;
        for (int j2 = 0; j2 < 64; j2++) {
            const ulonglong2* wa = (const ulonglong2*)(smf + OFF_W1P + (2*j2)  *28);
            const ulonglong2* wb = (const ulonglong2*)(smf + OFF_W1P + (2*j2+1)*28);
            u64 a0=0ull, a1=0ull, c0=0ull, c1=0ull;
#pragma unroll
            for (int q = 0; q < 7; q++) {
                ulonglong2 va = wa[q], vb = wb[q];
                a0 = ffma2(xp[2*q],   va.x, a0);
                a1 = ffma2(xp[2*q+1], va.y, a1);
                c0 = ffma2(xp[2*q],   vb.x, c0);
                c1 = ffma2(xp[2*q+1], vb.y, c1);
            }
            float l0,h0,l1,h1f;
            upk2(fadd2(a0,a1), l0, h0);
            upk2(fadd2(c0,c1), l1, h1f);
            float v0 = gelu_exact(l0 + h0  + smf[OFF_B1 + 2*j2]);
            float v1 = gelu_exact(l1 + h1f + smf[OFF_B1 + 2*j2 + 1]);
            sum1 += v0 + v1;  sq1 += v0*v0 + v1*v1;
            *(u64*)(stg + j2*512) = pk2(v0, v1);
        }
        float mu1 = sum1 * (1.0f/128.0f);
        float rs1 = rsqrtf(sq1 * (1.0f/128.0f) - mu1*mu1 + 1e-5f);
        float bco1 = rs1 * mu1;

        u64 h1v[64];
#pragma unroll
        for (int p = 0; p < 64; p++) h1v[p] = *(const u64*)(stg + p*512);

        // ---------------- layer 2 (LN1 folded) + GELU + layer 3 (LN2 folded) ----------------
        float sum2 = 0.f, sq2 = 0.f;
        u64 S0=0ull, S1=0ull, S2=0ull, S3=0ull;
        for (int j = 0; j < 128; j++) {
            const ulonglong2* wr = (const ulonglong2*)(smf + OFF_W2G + j*128);
            u64 a0=0ull, a1=0ull, a2=0ull, a3=0ull;
#pragma unroll
            for (int q = 0; q < 16; q++) {
                ulonglong2 w0 = wr[2*q], w1v = wr[2*q + 1];
                a0 = ffma2(h1v[4*q],     w0.x,  a0);
                a1 = ffma2(h1v[4*q + 1], w0.y,  a1);
                a2 = ffma2(h1v[4*q + 2], w1v.x, a2);
                a3 = ffma2(h1v[4*q + 3], w1v.y, a3);
            }
            float lo, hi;
            upk2(fadd2(fadd2(a0,a1), fadd2(a2,a3)), lo, hi);
            float T  = lo + hi;
            float hv = rs1*T - bco1*smf[OFF_G2 + j] + smf[OFF_C2 + j];
            float v  = gelu_exact(hv);
            sum2 += v;  sq2 += v*v;
            u64 vs = pk2(v, v);
            const ulonglong2* w3r = (const ulonglong2*)(smf + OFF_W3G + j*8);
            ulonglong2 wa3 = w3r[0], wb3 = w3r[1];
            S0 = ffma2(vs, wa3.x, S0);  S1 = ffma2(vs, wa3.y, S1);
            S2 = ffma2(vs, wb3.x, S2);  S3 = ffma2(vs, wb3.y, S3);
        }
        float mu2 = sum2 * (1.0f/128.0f);
        float rs2 = rsqrtf(sq2 * (1.0f/128.0f) - mu2*mu2 + 1e-5f);
        float bco2 = rs2 * mu2;
        float sv[8];
        upk2(S0, sv[0], sv[1]); upk2(S1, sv[2], sv[3]);
        upk2(S2, sv[4], sv[5]); upk2(S3, sv[6], sv[7]);

        const float ssi = (it == 0) ? ss0 : ((it == 1) ? ss1 : ss2);
        const float LO[7] = {-2.8973f, -1.7628f, -2.8973f, -3.0718f, -2.8973f, -0.0175f, -2.8973f};
        const float HI[7] = { 2.8973f,  1.7628f,  2.8973f, -0.0698f,  2.8973f,  3.7525f,  2.8973f};
#pragma unroll
        for (int jj = 0; jj < 7; jj++) {
            float dl = rs2*sv[jj] - bco2*smf[OFF_G3 + jj] + smf[OFF_C3 + jj];
            float nt = th[jj] + ssi * dl;
            th[jj] = fminf(fmaxf(nt, LO[jj]), HI[jj]);
        }
        float* pa = outAng + ((size_t)(it + 1) * B_TOT + s) * 7;
#pragma unroll
        for (int jj = 0; jj < 7; jj++) pa[jj] = th[jj];
    }

    // final outputs
#pragma unroll
    for (int jj = 0; jj < 7; jj++) outTheta[(size_t)s*7 + jj] = th[jj];
    float* pkf = outKp + (size_t)s * 21;
#pragma unroll
    for (int k = 0; k < 7; k++) { pkf[3*k]=kx[k]; pkf[3*k+1]=ky[k]; pkf[3*k+2]=kz[k]; }
}

extern "C" void kernel_launch(void* const* d_in, const int* in_sizes, int n_in,
                              void* d_out, int out_size) {
    (void)in_sizes; (void)n_in; (void)out_size;
    cudaFuncSetAttribute(irm_kernel, cudaFuncAttributeMaxDynamicSharedMemorySize, SMEM_BYTES);
    irm_kernel<<<BLOCKS, THREADS, SMEM_BYTES>>>(
        (const float*)d_in[0],           // initial_angles
        (const float*)d_in[1],           // target_2d
        (const float*)d_in[2],           // camera_K
        (const float*)d_in[4],           // R_ext   (d_in[3] = original_size, unused)
        (const float*)d_in[5],           // t_ext
        (const int*)d_in[6],             // valid_mask (bool normalized to int32 by harness)
        (const float*)d_in[7],  (const float*)d_in[8],
        (const float*)d_in[9],  (const float*)d_in[10],
        (const float*)d_in[11], (const float*)d_in[12],
        (const float*)d_in[13], (const float*)d_in[14],
        (const float*)d_in[15], (const float*)d_in[16],
        (const float*)d_in[17],
        (float*)d_out);
}